// round 1
// baseline (speedup 1.0000x reference)
#include <cuda_runtime.h>
#include <math.h>

#define BB   8
#define SS   16
#define IND  4096
#define HH   32
#define DD   128
#define PASTL 4096
#define KVL  4112
#define MM   128      /* B*S */
#define HD   4096     /* H*D */

static const size_t K_OFF    = (size_t)MM * IND;                 // 524288
static const size_t KV_ELEMS = (size_t)BB * HH * KVL * DD;       // 134742016
static const size_t V_OFF    = K_OFF + KV_ELEMS;

// Scratch (device globals: no allocation allowed)
__device__ float g_q[MM * HD];                 // [bh][s][d]
__device__ float g_attn[MM * HD];              // [m][h*128+d]  (A for O-proj)
__device__ float g_logits[BB * HH * SS * KVL]; // [bh][s][kv]  ~67 MB

// ---------------------------------------------------------------------------
// GEMM: Y[m,n] = sum_k A[m,128? no: m,4096] * W[n,4096]   (both K-contiguous)
// Tile 64x64, 128 threads, per-thread 8m x 4n, smem transposed for LDS.128.
// storeMode: 0=q scratch, 1=k_new->out, 2=v_new->out, 3=plain out
// ---------------------------------------------------------------------------
__global__ __launch_bounds__(128) void gemm_k(
    const float* __restrict__ A,
    const float* __restrict__ W0, const float* __restrict__ W1,
    const float* __restrict__ W2,
    float* __restrict__ dout, int mode)
{
    __shared__ float As[16 * 68];  // [kk][row(m)]
    __shared__ float Ws[16 * 64];  // [kk][row(n)]

    const float* Ap = A ? A : g_attn;
    const float* W  = (blockIdx.z == 0) ? W0 : (blockIdx.z == 1) ? W1 : W2;
    int storeMode   = (mode < 0) ? (int)blockIdx.z : mode;

    int t  = threadIdx.x;
    int m0 = blockIdx.y * 64;
    int n0 = blockIdx.x * 64;
    int tm = t >> 4;      // 0..7
    int tn = t & 15;      // 0..15

    float acc[8][4];
#pragma unroll
    for (int i = 0; i < 8; i++)
#pragma unroll
        for (int j = 0; j < 4; j++) acc[i][j] = 0.f;

    for (int k0 = 0; k0 < IND; k0 += 16) {
        // load A tile: 64 rows x 16 k  (256 float4)
#pragma unroll
        for (int rep = 0; rep < 2; rep++) {
            int i  = t + rep * 128;
            int r  = i >> 2, c4 = i & 3;
            float4 v = *(const float4*)(Ap + (size_t)(m0 + r) * IND + k0 + c4 * 4);
            As[(c4 * 4 + 0) * 68 + r] = v.x;
            As[(c4 * 4 + 1) * 68 + r] = v.y;
            As[(c4 * 4 + 2) * 68 + r] = v.z;
            As[(c4 * 4 + 3) * 68 + r] = v.w;
        }
        // load W tile: 64 rows x 16 k
#pragma unroll
        for (int rep = 0; rep < 2; rep++) {
            int i  = t + rep * 128;
            int r  = i >> 2, c4 = i & 3;
            float4 v = *(const float4*)(W + (size_t)(n0 + r) * IND + k0 + c4 * 4);
            Ws[(c4 * 4 + 0) * 64 + r] = v.x;
            Ws[(c4 * 4 + 1) * 64 + r] = v.y;
            Ws[(c4 * 4 + 2) * 64 + r] = v.z;
            Ws[(c4 * 4 + 3) * 64 + r] = v.w;
        }
        __syncthreads();
#pragma unroll
        for (int kk = 0; kk < 16; kk++) {
            float4 w  = *(const float4*)&Ws[kk * 64 + tn * 4];
            float4 a0 = *(const float4*)&As[kk * 68 + tm * 8];
            float4 a1 = *(const float4*)&As[kk * 68 + tm * 8 + 4];
            float av[8] = {a0.x, a0.y, a0.z, a0.w, a1.x, a1.y, a1.z, a1.w};
            float wv[4] = {w.x, w.y, w.z, w.w};
#pragma unroll
            for (int i = 0; i < 8; i++)
#pragma unroll
                for (int j = 0; j < 4; j++) acc[i][j] += av[i] * wv[j];
        }
        __syncthreads();
    }

    // store
#pragma unroll
    for (int i = 0; i < 8; i++) {
        int m = m0 + tm * 8 + i;
        int n = n0 + tn * 4;
        float4 r = make_float4(acc[i][0], acc[i][1], acc[i][2], acc[i][3]);
        if (storeMode == 3) {
            *(float4*)&dout[(size_t)m * HD + n] = r;
        } else {
            int b = m >> 4, s = m & 15, h = n >> 7, dd = n & 127;
            if (storeMode == 0) {
                *(float4*)&g_q[((size_t)(b * HH + h) * SS + s) * DD + dd] = r;
            } else {
                size_t off = (storeMode == 1) ? K_OFF : V_OFF;
                *(float4*)&dout[off + ((size_t)(b * HH + h) * KVL + PASTL + s) * DD + dd] = r;
            }
        }
    }
}

// ---------------------------------------------------------------------------
// Logits + fused K copy. Grid: (65 chunks of 64 kv, 256 bh). 128 threads.
// ---------------------------------------------------------------------------
__global__ __launch_bounds__(128) void logits_k(
    const float* __restrict__ kcache, const int* __restrict__ mask,
    float* __restrict__ dout)
{
    __shared__ float qs[SS * DD];      // broadcast reads, no pad
    __shared__ float ks[64 * 129];     // pad 129: conflict-free column reads

    int bh    = blockIdx.y;
    int kv0   = blockIdx.x * 64;
    int rows  = min(64, KVL - kv0);
    int t     = threadIdx.x;

    const float* qsrc = g_q + (size_t)bh * SS * DD;
#pragma unroll
    for (int i = t; i < SS * DD / 4; i += 128)
        ((float4*)qs)[i] = ((const float4*)qsrc)[i];

    float* kout = dout + K_OFF + (size_t)bh * KVL * DD;
    for (int i = t; i < rows * 32; i += 128) {
        int r = i >> 5, c4 = i & 31;
        int kv = kv0 + r;
        const float* src = (kv < PASTL)
            ? (kcache + ((size_t)bh * PASTL + kv) * DD)
            : (kout + (size_t)kv * DD);
        float4 v = ((const float4*)src)[c4];
        float* p = &ks[r * 129 + c4 * 4];
        p[0] = v.x; p[1] = v.y; p[2] = v.z; p[3] = v.w;
        if (kv < PASTL) ((float4*)(kout + (size_t)kv * DD))[c4] = v;
    }
    for (int i = rows * 32 + t; i < 64 * 32; i += 128) {
        int r = i >> 5, c4 = i & 31;
        float* p = &ks[r * 129 + c4 * 4];
        p[0] = p[1] = p[2] = p[3] = 0.f;
    }
    __syncthreads();

    int kvl = t & 31;    // 0..31
    int sg  = t >> 5;    // 0..3, warp-uniform
    float acc[4][2];
#pragma unroll
    for (int i = 0; i < 4; i++) { acc[i][0] = 0.f; acc[i][1] = 0.f; }

#pragma unroll 8
    for (int k = 0; k < 128; k++) {
        float k0v = ks[kvl * 129 + k];
        float k1v = ks[(kvl + 32) * 129 + k];
#pragma unroll
        for (int i = 0; i < 4; i++) {
            float q = qs[(sg * 4 + i) * 128 + k];
            acc[i][0] += q * k0v;
            acc[i][1] += q * k1v;
        }
    }

    const float scale = 0.08838834764831845f; // 1/sqrt(128)
    int b = bh >> 5;
#pragma unroll
    for (int j = 0; j < 2; j++) {
        int kvloc = kvl + j * 32;
        if (kvloc < rows) {
            int kv = kv0 + kvloc;
#pragma unroll
            for (int i = 0; i < 4; i++) {
                int s = sg * 4 + i;
                float lg = acc[i][j] * scale;
                int mv = mask[(size_t)(b * SS + s) * KVL + kv];
                if (mv == 0) lg = -1e30f;
                g_logits[((size_t)bh * SS + s) * KVL + kv] = lg;
            }
        }
    }
}

// ---------------------------------------------------------------------------
// Softmax in place over g_logits rows. Grid: B*H*S = 4096, 256 threads.
// ---------------------------------------------------------------------------
__global__ __launch_bounds__(256) void softmax_k()
{
    __shared__ float red[256];
    float* p = g_logits + (size_t)blockIdx.x * KVL;
    int t = threadIdx.x;

    float mx = -3.4e38f;
    for (int i = t; i < KVL; i += 256) mx = fmaxf(mx, p[i]);
    red[t] = mx; __syncthreads();
    for (int s = 128; s > 0; s >>= 1) {
        if (t < s) red[t] = fmaxf(red[t], red[t + s]);
        __syncthreads();
    }
    float m = red[0]; __syncthreads();

    float sum = 0.f;
    for (int i = t; i < KVL; i += 256) {
        float e = __expf(p[i] - m);
        p[i] = e;
        sum += e;
    }
    red[t] = sum; __syncthreads();
    for (int s = 128; s > 0; s >>= 1) {
        if (t < s) red[t] += red[t + s];
        __syncthreads();
    }
    float inv = 1.0f / red[0];
    for (int i = t; i < KVL; i += 256) p[i] *= inv;
}

// ---------------------------------------------------------------------------
// attn @ V + fused V copy. Grid: 256 (bh). 256 threads.
// Thread = (sg 0..7, dg 0..31): accumulates 2 s x 4 d.
// ---------------------------------------------------------------------------
__global__ __launch_bounds__(256) void av_k(
    const float* __restrict__ vcache, float* __restrict__ dout)
{
    __shared__ float vs[64 * 132];   // pad to 132: 16B-aligned rows
    __shared__ float ps[SS * 64];

    int bh = blockIdx.x;
    int t  = threadIdx.x;
    int dg = t & 31;   // d group (4 floats)
    int sg = t >> 5;   // 0..7, warp-uniform

    float acc[2][4];
#pragma unroll
    for (int i = 0; i < 2; i++)
#pragma unroll
        for (int j = 0; j < 4; j++) acc[i][j] = 0.f;

    float* vout = dout + V_OFF + (size_t)bh * KVL * DD;
    const float* pl = g_logits + (size_t)bh * SS * KVL;

    for (int kv0 = 0; kv0 < KVL; kv0 += 64) {
        int rows = min(64, KVL - kv0);
        for (int i = t; i < rows * 32; i += 256) {
            int r = i >> 5, c4 = i & 31;
            int kv = kv0 + r;
            const float* src = (kv < PASTL)
                ? (vcache + ((size_t)bh * PASTL + kv) * DD)
                : (vout + (size_t)kv * DD);
            float4 v = ((const float4*)src)[c4];
            float* q = &vs[r * 132 + c4 * 4];
            q[0] = v.x; q[1] = v.y; q[2] = v.z; q[3] = v.w;
            if (kv < PASTL) ((float4*)(vout + (size_t)kv * DD))[c4] = v;
        }
        for (int i = t; i < SS * 64; i += 256) {
            int s = i >> 6, c = i & 63;
            ps[i] = (c < rows) ? pl[(size_t)s * KVL + kv0 + c] : 0.f;
        }
        __syncthreads();

        for (int kv = 0; kv < rows; kv++) {
            float4 v = *(const float4*)&vs[kv * 132 + dg * 4];
#pragma unroll
            for (int i = 0; i < 2; i++) {
                float p = ps[(sg + i * 8) * 64 + kv];
                acc[i][0] += p * v.x;
                acc[i][1] += p * v.y;
                acc[i][2] += p * v.z;
                acc[i][3] += p * v.w;
            }
        }
        __syncthreads();
    }

    int b = bh >> 5, h = bh & 31;
#pragma unroll
    for (int i = 0; i < 2; i++) {
        int s = sg + i * 8;
        float4 r = make_float4(acc[i][0], acc[i][1], acc[i][2], acc[i][3]);
        *(float4*)&g_attn[(size_t)(b * SS + s) * HD + h * DD + dg * 4] = r;
    }
}

// ---------------------------------------------------------------------------
extern "C" void kernel_launch(void* const* d_in, const int* in_sizes, int n_in,
                              void* d_out, int out_size)
{
    const float* hidden = (const float*)d_in[0];
    const int*   mask   = (const int*)d_in[1];
    const float* kcache = (const float*)d_in[2];
    const float* vcache = (const float*)d_in[3];
    const float* Wq     = (const float*)d_in[4];
    const float* Wk     = (const float*)d_in[5];
    const float* Wv     = (const float*)d_in[6];
    const float* Wo     = (const float*)d_in[7];
    float* out = (float*)d_out;

    // 1. QKV projections (q -> scratch, k_new/v_new -> output tensors)
    dim3 gq(64, 2, 3);
    gemm_k<<<gq, 128>>>(hidden, Wq, Wk, Wv, out, -1);

    // 2. Logits + fused K-cache copy
    dim3 gl(65, 256);
    logits_k<<<gl, 128>>>(kcache, mask, out);

    // 3. Softmax
    softmax_k<<<BB * HH * SS, 256>>>();

    // 4. attn @ V + fused V-cache copy
    av_k<<<BB * HH, 256>>>(vcache, out);

    // 5. Output projection (A = g_attn via nullptr)
    dim3 go(64, 2, 1);
    gemm_k<<<go, 128>>>(nullptr, Wo, Wo, Wo, out, 3);
}

// round 2
// speedup vs baseline: 1.1537x; 1.1537x over previous
#include <cuda_runtime.h>
#include <math.h>

#define BB   8
#define SS   16
#define IND  4096
#define HH   32
#define DD   128
#define PASTL 4096
#define KVL  4112
#define MM   128      /* B*S */
#define HD   4096     /* H*D */
#define CHUNK 128
#define NSPLIT 33     /* ceil(4112/128) */

static const size_t K_OFF    = (size_t)MM * IND;                 // 524288
static const size_t KV_ELEMS = (size_t)BB * HH * KVL * DD;       // 134742016
static const size_t V_OFF    = K_OFF + KV_ELEMS;

// Scratch (device globals: no allocation allowed)
__device__ float g_q[MM * HD];                  // [bh][s][d]
__device__ float g_attn[MM * HD];               // [m][h*128+d]  (A for O-proj)
__device__ float g_pacc[(size_t)NSPLIT * 256 * SS * DD];  // split partial O
__device__ float g_pm[(size_t)NSPLIT * 256 * SS];         // split row max
__device__ float g_pl[(size_t)NSPLIT * 256 * SS];         // split row sum

// ---------------------------------------------------------------------------
// GEMM: Y[m,n] = sum_k A[m,4096] * W[n,4096]   (both K-contiguous)
// Tile 64x64, 128 threads, per-thread 8m x 4n, smem transposed for LDS.128.
// storeMode: 0=q scratch, 1=k_new->out, 2=v_new->out, 3=plain out
// ---------------------------------------------------------------------------
__global__ __launch_bounds__(128) void gemm_k(
    const float* __restrict__ A,
    const float* __restrict__ W0, const float* __restrict__ W1,
    const float* __restrict__ W2,
    float* __restrict__ dout, int mode)
{
    __shared__ float As[16 * 68];  // [kk][row(m)]
    __shared__ float Ws[16 * 64];  // [kk][row(n)]

    const float* Ap = A ? A : g_attn;
    const float* W  = (blockIdx.z == 0) ? W0 : (blockIdx.z == 1) ? W1 : W2;
    int storeMode   = (mode < 0) ? (int)blockIdx.z : mode;

    int t  = threadIdx.x;
    int m0 = blockIdx.y * 64;
    int n0 = blockIdx.x * 64;
    int tm = t >> 4;      // 0..7
    int tn = t & 15;      // 0..15

    float acc[8][4];
#pragma unroll
    for (int i = 0; i < 8; i++)
#pragma unroll
        for (int j = 0; j < 4; j++) acc[i][j] = 0.f;

    for (int k0 = 0; k0 < IND; k0 += 16) {
#pragma unroll
        for (int rep = 0; rep < 2; rep++) {
            int i  = t + rep * 128;
            int r  = i >> 2, c4 = i & 3;
            float4 v = *(const float4*)(Ap + (size_t)(m0 + r) * IND + k0 + c4 * 4);
            As[(c4 * 4 + 0) * 68 + r] = v.x;
            As[(c4 * 4 + 1) * 68 + r] = v.y;
            As[(c4 * 4 + 2) * 68 + r] = v.z;
            As[(c4 * 4 + 3) * 68 + r] = v.w;
        }
#pragma unroll
        for (int rep = 0; rep < 2; rep++) {
            int i  = t + rep * 128;
            int r  = i >> 2, c4 = i & 3;
            float4 v = *(const float4*)(W + (size_t)(n0 + r) * IND + k0 + c4 * 4);
            Ws[(c4 * 4 + 0) * 64 + r] = v.x;
            Ws[(c4 * 4 + 1) * 64 + r] = v.y;
            Ws[(c4 * 4 + 2) * 64 + r] = v.z;
            Ws[(c4 * 4 + 3) * 64 + r] = v.w;
        }
        __syncthreads();
#pragma unroll
        for (int kk = 0; kk < 16; kk++) {
            float4 w  = *(const float4*)&Ws[kk * 64 + tn * 4];
            float4 a0 = *(const float4*)&As[kk * 68 + tm * 8];
            float4 a1 = *(const float4*)&As[kk * 68 + tm * 8 + 4];
            float av[8] = {a0.x, a0.y, a0.z, a0.w, a1.x, a1.y, a1.z, a1.w};
            float wv[4] = {w.x, w.y, w.z, w.w};
#pragma unroll
            for (int i = 0; i < 8; i++)
#pragma unroll
                for (int j = 0; j < 4; j++) acc[i][j] += av[i] * wv[j];
        }
        __syncthreads();
    }

#pragma unroll
    for (int i = 0; i < 8; i++) {
        int m = m0 + tm * 8 + i;
        int n = n0 + tn * 4;
        float4 r = make_float4(acc[i][0], acc[i][1], acc[i][2], acc[i][3]);
        if (storeMode == 3) {
            *(float4*)&dout[(size_t)m * HD + n] = r;
        } else {
            int b = m >> 4, s = m & 15, h = n >> 7, dd = n & 127;
            if (storeMode == 0) {
                *(float4*)&g_q[((size_t)(b * HH + h) * SS + s) * DD + dd] = r;
            } else {
                size_t off = (storeMode == 1) ? K_OFF : V_OFF;
                *(float4*)&dout[off + ((size_t)(b * HH + h) * KVL + PASTL + s) * DD + dd] = r;
            }
        }
    }
}

// ---------------------------------------------------------------------------
// Split-KV flash attention + fused K/V cache copy.
// Grid (NSPLIT, 256 bh), 128 threads. Dynamic smem ~80.4KB, 2 blocks/SM.
// Smem: kvs[128][128] XOR-swizzled (K then V), qs[16][128], ps[16][132],
//       m_s[16], l_s[16].
// ---------------------------------------------------------------------------
__global__ __launch_bounds__(128) void flash_k(
    const float* __restrict__ kcache, const float* __restrict__ vcache,
    const int* __restrict__ mask, float* __restrict__ dout)
{
    extern __shared__ float sm[];
    float4* kvs4 = (float4*)sm;            // 16384 floats (4096 f4)
    float4* qs4  = (float4*)(sm + 16384);  // 2048 floats  (512 f4)
    float*  ps   = sm + 18432;             // 2112 floats  [16][132]
    float*  m_s  = sm + 20544;             // 16
    float*  l_s  = sm + 20560;             // 16

    int split = blockIdx.x;
    int bh    = blockIdx.y;
    int b     = bh >> 5;
    int kv0   = split * CHUNK;
    int rows  = min(CHUNK, KVL - kv0);
    int t     = threadIdx.x;
    int lane  = t & 31;

    // ---- Q load ----
    const float4* qsrc = (const float4*)(g_q + (size_t)bh * SS * DD);
#pragma unroll
    for (int i = t; i < 512; i += 128) qs4[i] = qsrc[i];

    // ---- K tile load (swizzled) + fused K-cache copy ----
    float* kout = dout + K_OFF + (size_t)bh * KVL * DD;
    for (int i = t; i < rows * 32; i += 128) {
        int r = i >> 5, c = i & 31;
        int kv = kv0 + r;
        const float4* src = (kv < PASTL)
            ? (const float4*)(kcache + ((size_t)bh * PASTL + kv) * DD)
            : (const float4*)(kout + (size_t)kv * DD);
        float4 v = src[c];
        kvs4[r * 32 + (c ^ (r & 7))] = v;
        if (kv < PASTL) ((float4*)(kout + (size_t)kv * DD))[c] = v;
    }
    for (int i = rows * 32 + t; i < 128 * 32; i += 128) {
        int r = i >> 5, c = i & 31;
        kvs4[r * 32 + (c ^ (r & 7))] = make_float4(0.f, 0.f, 0.f, 0.f);
    }
    __syncthreads();

    // ---- S = Q K^T : thread (sgrp = t>>5 -> 4 s rows, kvc = t&31 -> kv cols kvc+32j)
    int sgrp = t >> 5;
    int kvc  = lane;
    int s0   = sgrp * 4;
    {
        float acc[4][4];
#pragma unroll
        for (int i = 0; i < 4; i++)
#pragma unroll
            for (int j = 0; j < 4; j++) acc[i][j] = 0.f;

#pragma unroll 4
        for (int k4 = 0; k4 < 32; k4++) {
            float4 kf[4];
#pragma unroll
            for (int j = 0; j < 4; j++) {
                int kv = kvc + 32 * j;
                kf[j] = kvs4[kv * 32 + (k4 ^ (kv & 7))];
            }
#pragma unroll
            for (int i = 0; i < 4; i++) {
                float4 q = qs4[(s0 + i) * 32 + k4];
#pragma unroll
                for (int j = 0; j < 4; j++) {
                    acc[i][j] += q.x * kf[j].x + q.y * kf[j].y
                               + q.z * kf[j].z + q.w * kf[j].w;
                }
            }
        }

        const float scale = 0.08838834764831845f;  // 1/sqrt(128)
#pragma unroll
        for (int i = 0; i < 4; i++) {
            int s = s0 + i;
#pragma unroll
            for (int j = 0; j < 4; j++) {
                int kv  = kvc + 32 * j;
                int kvg = kv0 + kv;
                float lg;
                if (kvg >= KVL) lg = -1e30f;
                else {
                    lg = acc[i][j] * scale;
                    if (mask[(size_t)(b * SS + s) * KVL + kvg] == 0) lg = -1e30f;
                }
                ps[s * 132 + kv] = lg;
            }
        }
    }
    __syncthreads();

    // ---- row max (4 warps x 4 rows) ----
#pragma unroll
    for (int rr = 0; rr < 4; rr++) {
        int row = sgrp * 4 + rr;
        float v = fmaxf(fmaxf(ps[row * 132 + lane], ps[row * 132 + lane + 32]),
                        fmaxf(ps[row * 132 + lane + 64], ps[row * 132 + lane + 96]));
#pragma unroll
        for (int o = 16; o > 0; o >>= 1) v = fmaxf(v, __shfl_xor_sync(0xffffffffu, v, o));
        if (lane == 0) m_s[row] = v;
    }
    __syncthreads();

    // ---- exp pass (own cells) + V tile load (swizzled) + fused V copy ----
#pragma unroll
    for (int i = 0; i < 4; i++) {
        float m = m_s[s0 + i];
#pragma unroll
        for (int j = 0; j < 4; j++) {
            float* p = &ps[(s0 + i) * 132 + kvc + 32 * j];
            *p = __expf(*p - m);
        }
    }
    float* vout = dout + V_OFF + (size_t)bh * KVL * DD;
    for (int i = t; i < rows * 32; i += 128) {
        int r = i >> 5, c = i & 31;
        int kv = kv0 + r;
        const float4* src = (kv < PASTL)
            ? (const float4*)(vcache + ((size_t)bh * PASTL + kv) * DD)
            : (const float4*)(vout + (size_t)kv * DD);
        float4 v = src[c];
        kvs4[r * 32 + (c ^ (r & 7))] = v;
        if (kv < PASTL) ((float4*)(vout + (size_t)kv * DD))[c] = v;
    }
    for (int i = rows * 32 + t; i < 128 * 32; i += 128) {
        int r = i >> 5, c = i & 31;
        kvs4[r * 32 + (c ^ (r & 7))] = make_float4(0.f, 0.f, 0.f, 0.f);
    }
    __syncthreads();

    // ---- row sum ----
#pragma unroll
    for (int rr = 0; rr < 4; rr++) {
        int row = sgrp * 4 + rr;
        float v = ps[row * 132 + lane] + ps[row * 132 + lane + 32]
                + ps[row * 132 + lane + 64] + ps[row * 132 + lane + 96];
#pragma unroll
        for (int o = 16; o > 0; o >>= 1) v += __shfl_xor_sync(0xffffffffu, v, o);
        if (lane == 0) l_s[row] = v;
    }
    __syncthreads();

    // ---- O_partial = P V : thread (sga = t>>5 -> 4 s rows, dg = t&31 -> 4 d)
    {
        int dg  = lane;
        int sga = sgrp;
        float4 oacc[4];
#pragma unroll
        for (int i = 0; i < 4; i++) oacc[i] = make_float4(0.f, 0.f, 0.f, 0.f);

        const float4* ps4 = (const float4*)ps;  // row stride 33 f4
#pragma unroll 4
        for (int kv4 = 0; kv4 < 32; kv4++) {
            float4 vv[4];
#pragma unroll
            for (int j = 0; j < 4; j++) {
                int kv = kv4 * 4 + j;
                vv[j] = kvs4[kv * 32 + (dg ^ (kv & 7))];
            }
#pragma unroll
            for (int i = 0; i < 4; i++) {
                float4 p4 = ps4[(sga * 4 + i) * 33 + kv4];
                oacc[i].x += p4.x * vv[0].x + p4.y * vv[1].x + p4.z * vv[2].x + p4.w * vv[3].x;
                oacc[i].y += p4.x * vv[0].y + p4.y * vv[1].y + p4.z * vv[2].y + p4.w * vv[3].y;
                oacc[i].z += p4.x * vv[0].z + p4.y * vv[1].z + p4.z * vv[2].z + p4.w * vv[3].z;
                oacc[i].w += p4.x * vv[0].w + p4.y * vv[1].w + p4.z * vv[2].w + p4.w * vv[3].w;
            }
        }

        size_t base = ((size_t)split * 256 + bh) * (SS * DD);
#pragma unroll
        for (int i = 0; i < 4; i++) {
            int s = sga * 4 + i;
            ((float4*)(g_pacc + base + (size_t)s * DD))[dg] = oacc[i];
        }
    }
    if (t < 16) {
        size_t idx = ((size_t)split * 256 + bh) * SS + t;
        g_pm[idx] = m_s[t];
        g_pl[idx] = l_s[t];
    }
}

// ---------------------------------------------------------------------------
// Combine split partials -> g_attn. Grid 256 (bh), 128 threads.
// ---------------------------------------------------------------------------
__global__ __launch_bounds__(128) void combine_k()
{
    int bh = blockIdx.x;
    int t  = threadIdx.x;
    int dg = t & 31, sga = t >> 5;
    int b = bh >> 5, h = bh & 31;

#pragma unroll
    for (int i = 0; i < 4; i++) {
        int s = sga * 4 + i;
        float M = -3.4e38f;
        for (int sp = 0; sp < NSPLIT; sp++)
            M = fmaxf(M, g_pm[((size_t)sp * 256 + bh) * SS + s]);
        float lsum = 0.f;
        float4 o = make_float4(0.f, 0.f, 0.f, 0.f);
        for (int sp = 0; sp < NSPLIT; sp++) {
            size_t idx = (size_t)sp * 256 + bh;
            float f = __expf(g_pm[idx * SS + s] - M);
            lsum += f * g_pl[idx * SS + s];
            float4 a = ((const float4*)(g_pacc + idx * (SS * DD) + (size_t)s * DD))[dg];
            o.x += f * a.x; o.y += f * a.y; o.z += f * a.z; o.w += f * a.w;
        }
        float inv = 1.0f / lsum;
        o.x *= inv; o.y *= inv; o.z *= inv; o.w *= inv;
        ((float4*)(g_attn + ((size_t)(b * SS + s)) * HD + h * DD))[dg] = o;
    }
}

// ---------------------------------------------------------------------------
extern "C" void kernel_launch(void* const* d_in, const int* in_sizes, int n_in,
                              void* d_out, int out_size)
{
    const float* hidden = (const float*)d_in[0];
    const int*   mask   = (const int*)d_in[1];
    const float* kcache = (const float*)d_in[2];
    const float* vcache = (const float*)d_in[3];
    const float* Wq     = (const float*)d_in[4];
    const float* Wk     = (const float*)d_in[5];
    const float* Wv     = (const float*)d_in[6];
    const float* Wo     = (const float*)d_in[7];
    float* out = (float*)d_out;

    // flash_k needs >48KB dynamic smem
    const int FLASH_SMEM = (16384 + 2048 + 2112 + 32) * 4;  // 82304 B
    cudaFuncSetAttribute(flash_k, cudaFuncAttributeMaxDynamicSharedMemorySize,
                         FLASH_SMEM);

    // 1. QKV projections (q -> scratch, k_new/v_new -> output tensors)
    dim3 gq(64, 2, 3);
    gemm_k<<<gq, 128>>>(hidden, Wq, Wk, Wv, out, -1);

    // 2. Split-KV flash attention + fused K/V cache copies
    dim3 gf(NSPLIT, 256);
    flash_k<<<gf, 128, FLASH_SMEM>>>(kcache, vcache, mask, out);

    // 3. Combine split partials
    combine_k<<<256, 128>>>();

    // 4. Output projection (A = g_attn via nullptr)
    dim3 go(64, 2, 1);
    gemm_k<<<go, 128>>>(nullptr, Wo, Wo, Wo, out, 3);
}

// round 3
// speedup vs baseline: 1.4243x; 1.2346x over previous
#include <cuda_runtime.h>
#include <math.h>

#define BB   8
#define SS   16
#define IND  4096
#define HH   32
#define DD   128
#define PASTL 4096
#define KVL  4112
#define MM   128      /* B*S */
#define HD   4096     /* H*D */
#define CHUNK 128
#define NSPLIT 33     /* ceil(4112/128) */
#define KSPLIT 4
#define KCH  (IND / KSPLIT)   /* 1024 */

static const size_t K_OFF    = (size_t)MM * IND;                 // 524288
static const size_t KV_ELEMS = (size_t)BB * HH * KVL * DD;       // 134742016
static const size_t V_OFF    = K_OFF + KV_ELEMS;

// Scratch (device globals: no allocation allowed)
__device__ float g_q[MM * HD];                   // [bh][s][d]
__device__ float g_attn[MM * HD];                // [m][h*128+d]
__device__ float g_part[(size_t)KSPLIT * MM * 3 * HD];    // split-K partials (25MB)
__device__ float g_pacc[(size_t)NSPLIT * 256 * SS * DD];  // flash partial O
__device__ float g_pm[(size_t)NSPLIT * 256 * SS];
__device__ float g_pl[(size_t)NSPLIT * 256 * SS];

// ---------------- f32x2 helpers ----------------
__device__ __forceinline__ void fma2(unsigned long long& acc,
                                     unsigned long long a, unsigned long long b)
{
    asm("fma.rn.f32x2 %0, %1, %2, %0;" : "+l"(acc) : "l"(a), "l"(b));
}
__device__ __forceinline__ unsigned long long dup2(float x)
{
    unsigned long long r;
    unsigned int u = __float_as_uint(x);
    asm("mov.b64 %0, {%1, %1};" : "=l"(r) : "r"(u));
    return r;
}
__device__ __forceinline__ float2 unpk(unsigned long long v)
{
    unsigned int lo, hi;
    asm("mov.b64 {%0, %1}, %2;" : "=r"(lo), "=r"(hi) : "l"(v));
    return make_float2(__uint_as_float(lo), __uint_as_float(hi));
}

// ---------------------------------------------------------------------------
// Split-K GEMM, f32x2. Y[m, zn] = sum_k A[m,:] W_z[n,:]. Tile M=128 x N=64.
// 128 threads, per-thread 8m x 8n (as 4 m-pairs x 8n f32x2 accumulators).
// Partials -> g_part[(split*128+m)*NT + z*4096 + n].
// ---------------------------------------------------------------------------
__global__ __launch_bounds__(128) void gemm2_k(
    const float* __restrict__ A,
    const float* __restrict__ W0, const float* __restrict__ W1,
    const float* __restrict__ W2, int NT)
{
    __shared__ float As[16 * 132];  // [kk][m], pad 132
    __shared__ float Ws[16 * 68];   // [kk][n], pad 68

    const float* Ap = A ? A : g_attn;
    const float* W  = (blockIdx.z == 0) ? W0 : (blockIdx.z == 1) ? W1 : W2;

    int t     = threadIdx.x;
    int n0    = blockIdx.x * 64;
    int split = blockIdx.y;
    int z     = blockIdx.z;
    int tm    = t >> 3;   // 0..15 -> 8 m rows
    int tn    = t & 7;    // 0..7  -> 8 n cols

    unsigned long long acc[4][8];
#pragma unroll
    for (int i = 0; i < 4; i++)
#pragma unroll
        for (int j = 0; j < 8; j++) acc[i][j] = 0ULL;

    int kbeg = split * KCH;
    for (int k0 = kbeg; k0 < kbeg + KCH; k0 += 16) {
        // A tile: 128 rows x 16 k (512 float4)
#pragma unroll
        for (int rep = 0; rep < 4; rep++) {
            int i  = t + rep * 128;
            int r  = i >> 2, c4 = i & 3;
            float4 v = *(const float4*)(Ap + (size_t)r * IND + k0 + c4 * 4);
            As[(c4 * 4 + 0) * 132 + r] = v.x;
            As[(c4 * 4 + 1) * 132 + r] = v.y;
            As[(c4 * 4 + 2) * 132 + r] = v.z;
            As[(c4 * 4 + 3) * 132 + r] = v.w;
        }
        // W tile: 64 rows x 16 k (256 float4)
#pragma unroll
        for (int rep = 0; rep < 2; rep++) {
            int i  = t + rep * 128;
            int r  = i >> 2, c4 = i & 3;
            float4 v = *(const float4*)(W + (size_t)(n0 + r) * IND + k0 + c4 * 4);
            Ws[(c4 * 4 + 0) * 68 + r] = v.x;
            Ws[(c4 * 4 + 1) * 68 + r] = v.y;
            Ws[(c4 * 4 + 2) * 68 + r] = v.z;
            Ws[(c4 * 4 + 3) * 68 + r] = v.w;
        }
        __syncthreads();
#pragma unroll
        for (int kk = 0; kk < 16; kk++) {
            ulonglong2 a0 = *(const ulonglong2*)&As[kk * 132 + tm * 8];
            ulonglong2 a1 = *(const ulonglong2*)&As[kk * 132 + tm * 8 + 4];
            float4 w0 = *(const float4*)&Ws[kk * 68 + tn * 8];
            float4 w1 = *(const float4*)&Ws[kk * 68 + tn * 8 + 4];
            unsigned long long am[4] = {a0.x, a0.y, a1.x, a1.y};
            unsigned long long wd[8] = {dup2(w0.x), dup2(w0.y), dup2(w0.z), dup2(w0.w),
                                        dup2(w1.x), dup2(w1.y), dup2(w1.z), dup2(w1.w)};
#pragma unroll
            for (int mp = 0; mp < 4; mp++)
#pragma unroll
                for (int j = 0; j < 8; j++) fma2(acc[mp][j], am[mp], wd[j]);
        }
        __syncthreads();
    }

    // store partials
    int col0 = z * 4096 + n0 + tn * 8;
#pragma unroll
    for (int mp = 0; mp < 4; mp++) {
        float2 r[8];
#pragma unroll
        for (int j = 0; j < 8; j++) r[j] = unpk(acc[mp][j]);
        int mlo = tm * 8 + 2 * mp;
        size_t blo = (size_t)(split * MM + mlo) * NT + col0;
        size_t bhi = blo + NT;
        *(float4*)&g_part[blo]     = make_float4(r[0].x, r[1].x, r[2].x, r[3].x);
        *(float4*)&g_part[blo + 4] = make_float4(r[4].x, r[5].x, r[6].x, r[7].x);
        *(float4*)&g_part[bhi]     = make_float4(r[0].y, r[1].y, r[2].y, r[3].y);
        *(float4*)&g_part[bhi + 4] = make_float4(r[4].y, r[5].y, r[6].y, r[7].y);
    }
}

// ---------------------------------------------------------------------------
// Reduce split-K partials for QKV and route. 393216 float4s.
// ---------------------------------------------------------------------------
__global__ __launch_bounds__(256) void reduce_qkv_k(float* __restrict__ dout)
{
    int i = blockIdx.x * 256 + threadIdx.x;        // float4 index
    int m = i / 3072, c = i - m * 3072;
    const float4* p = (const float4*)g_part;
    float4 s = p[(size_t)m * 3072 + c];
#pragma unroll
    for (int sp = 1; sp < KSPLIT; sp++) {
        float4 a = p[(size_t)(sp * MM + m) * 3072 + c];
        s.x += a.x; s.y += a.y; s.z += a.z; s.w += a.w;
    }
    int n  = c * 4;
    int z  = n >> 12, nl = n & 4095;
    int h  = nl >> 7, dd = nl & 127;
    int b  = m >> 4, sq = m & 15;
    if (z == 0) {
        *(float4*)&g_q[((size_t)(b * HH + h) * SS + sq) * DD + dd] = s;
    } else {
        size_t off = (z == 1) ? K_OFF : V_OFF;
        *(float4*)&dout[off + ((size_t)(b * HH + h) * KVL + PASTL + sq) * DD + dd] = s;
    }
}

// Reduce split-K partials for O-projection. 131072 float4s.
__global__ __launch_bounds__(256) void reduce_o_k(float* __restrict__ dout)
{
    int i = blockIdx.x * 256 + threadIdx.x;
    int m = i / 1024, c = i - m * 1024;
    const float4* p = (const float4*)g_part;
    float4 s = p[(size_t)m * 1024 + c];
#pragma unroll
    for (int sp = 1; sp < KSPLIT; sp++) {
        float4 a = p[(size_t)(sp * MM + m) * 1024 + c];
        s.x += a.x; s.y += a.y; s.z += a.z; s.w += a.w;
    }
    *(float4*)&dout[(size_t)m * HD + c * 4] = s;
}

// ---------------------------------------------------------------------------
// Split-KV flash attention + fused K/V cache copy (f32x2 inner GEMMs).
// Grid (NSPLIT, 256 bh), 128 threads, ~80.4KB dyn smem, 2 blocks/SM.
// ---------------------------------------------------------------------------
__global__ __launch_bounds__(128) void flash_k(
    const float* __restrict__ kcache, const float* __restrict__ vcache,
    const int* __restrict__ mask, float* __restrict__ dout)
{
    extern __shared__ float sm[];
    float4* kvs4 = (float4*)sm;            // 4096 f4
    float4* qs4  = (float4*)(sm + 16384);  // 512 f4
    float*  ps   = sm + 18432;             // [16][132]
    float*  m_s  = sm + 20544;
    float*  l_s  = sm + 20560;
    const ulonglong2* kvsu = (const ulonglong2*)kvs4;
    const ulonglong2* qsu  = (const ulonglong2*)qs4;

    int split = blockIdx.x;
    int bh    = blockIdx.y;
    int b     = bh >> 5;
    int kv0   = split * CHUNK;
    int rows  = min(CHUNK, KVL - kv0);
    int t     = threadIdx.x;
    int lane  = t & 31;

    // ---- Q load ----
    const float4* qsrc = (const float4*)(g_q + (size_t)bh * SS * DD);
#pragma unroll
    for (int i = t; i < 512; i += 128) qs4[i] = qsrc[i];

    // ---- K tile load (swizzled) + fused K-cache copy ----
    float* kout = dout + K_OFF + (size_t)bh * KVL * DD;
    for (int i = t; i < rows * 32; i += 128) {
        int r = i >> 5, c = i & 31;
        int kv = kv0 + r;
        const float4* src = (kv < PASTL)
            ? (const float4*)(kcache + ((size_t)bh * PASTL + kv) * DD)
            : (const float4*)(kout + (size_t)kv * DD);
        float4 v = src[c];
        kvs4[r * 32 + (c ^ (r & 7))] = v;
        if (kv < PASTL) ((float4*)(kout + (size_t)kv * DD))[c] = v;
    }
    for (int i = rows * 32 + t; i < 128 * 32; i += 128) {
        int r = i >> 5, c = i & 31;
        kvs4[r * 32 + (c ^ (r & 7))] = make_float4(0.f, 0.f, 0.f, 0.f);
    }
    __syncthreads();

    // ---- S = Q K^T ----
    int sgrp = t >> 5;
    int kvc  = lane;
    int s0   = sgrp * 4;
    {
        unsigned long long acc2[4][4];
#pragma unroll
        for (int i = 0; i < 4; i++)
#pragma unroll
            for (int j = 0; j < 4; j++) acc2[i][j] = 0ULL;

#pragma unroll 4
        for (int k4 = 0; k4 < 32; k4++) {
            ulonglong2 kf[4];
#pragma unroll
            for (int j = 0; j < 4; j++) {
                int kv = kvc + 32 * j;
                kf[j] = kvsu[kv * 32 + (k4 ^ (kv & 7))];
            }
#pragma unroll
            for (int i = 0; i < 4; i++) {
                ulonglong2 q = qsu[(s0 + i) * 32 + k4];
#pragma unroll
                for (int j = 0; j < 4; j++) {
                    fma2(acc2[i][j], q.x, kf[j].x);
                    fma2(acc2[i][j], q.y, kf[j].y);
                }
            }
        }

        const float scale = 0.08838834764831845f;  // 1/sqrt(128)
#pragma unroll
        for (int i = 0; i < 4; i++) {
            int s = s0 + i;
#pragma unroll
            for (int j = 0; j < 4; j++) {
                int kv  = kvc + 32 * j;
                int kvg = kv0 + kv;
                float lg;
                if (kvg >= KVL) lg = -1e30f;
                else {
                    float2 f = unpk(acc2[i][j]);
                    lg = (f.x + f.y) * scale;
                    if (mask[(size_t)(b * SS + s) * KVL + kvg] == 0) lg = -1e30f;
                }
                ps[s * 132 + kv] = lg;
            }
        }
    }
    __syncthreads();

    // ---- row max ----
#pragma unroll
    for (int rr = 0; rr < 4; rr++) {
        int row = sgrp * 4 + rr;
        float v = fmaxf(fmaxf(ps[row * 132 + lane], ps[row * 132 + lane + 32]),
                        fmaxf(ps[row * 132 + lane + 64], ps[row * 132 + lane + 96]));
#pragma unroll
        for (int o = 16; o > 0; o >>= 1) v = fmaxf(v, __shfl_xor_sync(0xffffffffu, v, o));
        if (lane == 0) m_s[row] = v;
    }
    __syncthreads();

    // ---- exp pass + V tile load + fused V copy ----
#pragma unroll
    for (int i = 0; i < 4; i++) {
        float m = m_s[s0 + i];
#pragma unroll
        for (int j = 0; j < 4; j++) {
            float* p = &ps[(s0 + i) * 132 + kvc + 32 * j];
            *p = __expf(*p - m);
        }
    }
    float* vout = dout + V_OFF + (size_t)bh * KVL * DD;
    for (int i = t; i < rows * 32; i += 128) {
        int r = i >> 5, c = i & 31;
        int kv = kv0 + r;
        const float4* src = (kv < PASTL)
            ? (const float4*)(vcache + ((size_t)bh * PASTL + kv) * DD)
            : (const float4*)(vout + (size_t)kv * DD);
        float4 v = src[c];
        kvs4[r * 32 + (c ^ (r & 7))] = v;
        if (kv < PASTL) ((float4*)(vout + (size_t)kv * DD))[c] = v;
    }
    for (int i = rows * 32 + t; i < 128 * 32; i += 128) {
        int r = i >> 5, c = i & 31;
        kvs4[r * 32 + (c ^ (r & 7))] = make_float4(0.f, 0.f, 0.f, 0.f);
    }
    __syncthreads();

    // ---- row sum ----
#pragma unroll
    for (int rr = 0; rr < 4; rr++) {
        int row = sgrp * 4 + rr;
        float v = ps[row * 132 + lane] + ps[row * 132 + lane + 32]
                + ps[row * 132 + lane + 64] + ps[row * 132 + lane + 96];
#pragma unroll
        for (int o = 16; o > 0; o >>= 1) v += __shfl_xor_sync(0xffffffffu, v, o);
        if (lane == 0) l_s[row] = v;
    }
    __syncthreads();

    // ---- O_partial = P V ----
    {
        int dg  = lane;
        int sga = sgrp;
        unsigned long long o2[4][2];
#pragma unroll
        for (int i = 0; i < 4; i++) { o2[i][0] = 0ULL; o2[i][1] = 0ULL; }

        const float4* ps4 = (const float4*)ps;  // row stride 33 f4
#pragma unroll 4
        for (int kv4 = 0; kv4 < 32; kv4++) {
            ulonglong2 vv[4];
#pragma unroll
            for (int j = 0; j < 4; j++) {
                int kv = kv4 * 4 + j;
                vv[j] = kvsu[kv * 32 + (dg ^ (kv & 7))];
            }
#pragma unroll
            for (int i = 0; i < 4; i++) {
                float4 p4 = ps4[(sga * 4 + i) * 33 + kv4];
                unsigned long long pd;
                pd = dup2(p4.x); fma2(o2[i][0], pd, vv[0].x); fma2(o2[i][1], pd, vv[0].y);
                pd = dup2(p4.y); fma2(o2[i][0], pd, vv[1].x); fma2(o2[i][1], pd, vv[1].y);
                pd = dup2(p4.z); fma2(o2[i][0], pd, vv[2].x); fma2(o2[i][1], pd, vv[2].y);
                pd = dup2(p4.w); fma2(o2[i][0], pd, vv[3].x); fma2(o2[i][1], pd, vv[3].y);
            }
        }

        size_t base = ((size_t)split * 256 + bh) * (SS * DD);
#pragma unroll
        for (int i = 0; i < 4; i++) {
            int s = sga * 4 + i;
            float2 l0 = unpk(o2[i][0]);
            float2 l1 = unpk(o2[i][1]);
            ((float4*)(g_pacc + base + (size_t)s * DD))[dg] =
                make_float4(l0.x, l0.y, l1.x, l1.y);
        }
    }
    if (t < 16) {
        size_t idx = ((size_t)split * 256 + bh) * SS + t;
        g_pm[idx] = m_s[t];
        g_pl[idx] = l_s[t];
    }
}

// ---------------------------------------------------------------------------
// Combine split partials -> g_attn. Grid 256 (bh), 128 threads.
// ---------------------------------------------------------------------------
__global__ __launch_bounds__(128) void combine_k()
{
    int bh = blockIdx.x;
    int t  = threadIdx.x;
    int dg = t & 31, sga = t >> 5;
    int b = bh >> 5, h = bh & 31;

#pragma unroll
    for (int i = 0; i < 4; i++) {
        int s = sga * 4 + i;
        float M = -3.4e38f;
        for (int sp = 0; sp < NSPLIT; sp++)
            M = fmaxf(M, g_pm[((size_t)sp * 256 + bh) * SS + s]);
        float lsum = 0.f;
        float4 o = make_float4(0.f, 0.f, 0.f, 0.f);
        for (int sp = 0; sp < NSPLIT; sp++) {
            size_t idx = (size_t)sp * 256 + bh;
            float f = __expf(g_pm[idx * SS + s] - M);
            lsum += f * g_pl[idx * SS + s];
            float4 a = ((const float4*)(g_pacc + idx * (SS * DD) + (size_t)s * DD))[dg];
            o.x += f * a.x; o.y += f * a.y; o.z += f * a.z; o.w += f * a.w;
        }
        float inv = 1.0f / lsum;
        o.x *= inv; o.y *= inv; o.z *= inv; o.w *= inv;
        ((float4*)(g_attn + ((size_t)(b * SS + s)) * HD + h * DD))[dg] = o;
    }
}

// ---------------------------------------------------------------------------
extern "C" void kernel_launch(void* const* d_in, const int* in_sizes, int n_in,
                              void* d_out, int out_size)
{
    const float* hidden = (const float*)d_in[0];
    const int*   mask   = (const int*)d_in[1];
    const float* kcache = (const float*)d_in[2];
    const float* vcache = (const float*)d_in[3];
    const float* Wq     = (const float*)d_in[4];
    const float* Wk     = (const float*)d_in[5];
    const float* Wv     = (const float*)d_in[6];
    const float* Wo     = (const float*)d_in[7];
    float* out = (float*)d_out;

    const int FLASH_SMEM = (16384 + 2048 + 2112 + 32) * 4;  // 82304 B
    cudaFuncSetAttribute(flash_k, cudaFuncAttributeMaxDynamicSharedMemorySize,
                         FLASH_SMEM);

    // 1. QKV projections (split-K partials)
    gemm2_k<<<dim3(64, KSPLIT, 3), 128>>>(hidden, Wq, Wk, Wv, 12288);
    // 2. Reduce + route (q -> scratch, k_new/v_new -> out)
    reduce_qkv_k<<<1536, 256>>>(out);
    // 3. Split-KV flash attention + fused K/V cache copies
    flash_k<<<dim3(NSPLIT, 256), 128, FLASH_SMEM>>>(kcache, vcache, mask, out);
    // 4. Combine flash partials
    combine_k<<<256, 128>>>();
    // 5. Output projection (A = g_attn)
    gemm2_k<<<dim3(64, KSPLIT, 1), 128>>>(nullptr, Wo, Wo, Wo, 4096);
    reduce_o_k<<<512, 256>>>(out);
}

// round 6
// speedup vs baseline: 1.6088x; 1.1295x over previous
#include <cuda_runtime.h>
#include <cuda_bf16.h>
#include <math.h>
#include <stdint.h>

#define BB   8
#define SS   16
#define IND  4096
#define HH   32
#define DD   128
#define PASTL 4096
#define KVL  4112
#define MM   128      /* B*S */
#define HD   4096     /* H*D */
#define CHUNK 128
#define NSPLIT 33     /* ceil(4112/128) */
#define KCHUNK 64
#define NCH  (IND / KCHUNK)   /* 64 */

static const size_t K_OFF    = (size_t)MM * IND;                 // 524288
static const size_t KV_ELEMS = (size_t)BB * HH * KVL * DD;       // 134742016
static const size_t V_OFF    = K_OFF + KV_ELEMS;

// Scratch (device globals: no allocation allowed)
__device__ float g_q[MM * HD];                  // [bh][s][d]
__device__ float g_attn[MM * HD];               // [m][h*128+d]
__device__ float g_pacc[(size_t)NSPLIT * 256 * SS * DD];  // flash partial O
__device__ float g_pm[(size_t)NSPLIT * 256 * SS];
__device__ float g_pl[(size_t)NSPLIT * 256 * SS];

// ---------------- helpers ----------------
__device__ __forceinline__ uint32_t smem_u32(const void* p) {
    uint32_t a;
    asm("{ .reg .u64 t; cvta.to.shared.u64 t, %1; cvt.u32.u64 %0, t; }"
        : "=r"(a) : "l"(p));
    return a;
}
__device__ __forceinline__ void ldsm4(uint32_t* r, uint32_t addr) {
    asm volatile("ldmatrix.sync.aligned.m8n8.x4.shared.b16 {%0,%1,%2,%3}, [%4];"
        : "=r"(r[0]), "=r"(r[1]), "=r"(r[2]), "=r"(r[3]) : "r"(addr));
}
__device__ __forceinline__ void mma_bf16(float* d, const uint32_t* a,
                                         const uint32_t* b) {
    asm volatile(
        "mma.sync.aligned.m16n8k16.row.col.f32.bf16.bf16.f32 "
        "{%0,%1,%2,%3}, {%4,%5,%6,%7}, {%8,%9}, {%0,%1,%2,%3};"
        : "+f"(d[0]), "+f"(d[1]), "+f"(d[2]), "+f"(d[3])
        : "r"(a[0]), "r"(a[1]), "r"(a[2]), "r"(a[3]), "r"(b[0]), "r"(b[1]));
}

// f32x2 helpers for flash kernel
__device__ __forceinline__ void fma2(unsigned long long& acc,
                                     unsigned long long a, unsigned long long b)
{
    asm("fma.rn.f32x2 %0, %1, %2, %0;" : "+l"(acc) : "l"(a), "l"(b));
}
__device__ __forceinline__ unsigned long long dup2(float x)
{
    unsigned long long r;
    unsigned int u = __float_as_uint(x);
    asm("mov.b64 %0, {%1, %1};" : "=l"(r) : "r"(u));
    return r;
}
__device__ __forceinline__ float2 unpk(unsigned long long v)
{
    unsigned int lo, hi;
    asm("mov.b64 {%0, %1}, %2;" : "=r"(lo), "=r"(hi) : "l"(v));
    return make_float2(__uint_as_float(lo), __uint_as_float(hi));
}

// Convert float4 -> bf16 hi/lo pairs, store (8B each) at swizzled smem offsets.
// Row layout: 128 bytes (64 bf16). Swizzle: bits[4:6] ^= row&7.
__device__ __forceinline__ void cvt_store(uint32_t hiBase, uint32_t loBase,
                                          int r, int c4, float4 v) {
    uint32_t h0, h1;
    asm("cvt.rn.bf16x2.f32 %0, %1, %2;" : "=r"(h0) : "f"(v.y), "f"(v.x));
    asm("cvt.rn.bf16x2.f32 %0, %1, %2;" : "=r"(h1) : "f"(v.w), "f"(v.z));
    float hx = __uint_as_float(h0 << 16), hy = __uint_as_float(h0 & 0xFFFF0000u);
    float hz = __uint_as_float(h1 << 16), hw = __uint_as_float(h1 & 0xFFFF0000u);
    float lx = v.x - hx, ly = v.y - hy, lz = v.z - hz, lw = v.w - hw;
    uint32_t l0, l1;
    asm("cvt.rn.bf16x2.f32 %0, %1, %2;" : "=r"(l0) : "f"(ly), "f"(lx));
    asm("cvt.rn.bf16x2.f32 %0, %1, %2;" : "=r"(l1) : "f"(lw), "f"(lz));
    uint32_t off = (uint32_t)(r * 128 + c4 * 8);
    uint32_t sw  = off ^ (((uint32_t)(r & 7)) << 4);
    asm volatile("st.shared.v2.b32 [%0], {%1,%2};" :: "r"(hiBase + sw), "r"(h0), "r"(h1));
    asm volatile("st.shared.v2.b32 [%0], {%1,%2};" :: "r"(loBase + sw), "r"(l0), "r"(l1));
}

// ---------------------------------------------------------------------------
// bf16x3 MMA GEMM: Y[m,n] = sum_k A[m,k] * W[n,k]. M=128, N-tile NT.
// 256 threads = 8 warps (2m x 4n); warp tile 64m x (NT/4)n.
// A,W split hi/lo bf16 in smem; 3 mma terms approximate fp32.
// mode<0: QKV (z = bid/(HD/NT)), routes q/k_new/v_new. mode==3: plain out.
// ---------------------------------------------------------------------------
template<int NT>
__global__ __launch_bounds__(256) void gemm_mma(
    const float* __restrict__ A,
    const float* __restrict__ W0, const float* __restrict__ W1,
    const float* __restrict__ W2,
    float* __restrict__ dout, int mode)
{
    constexpr int WN = NT / 4;     // n per warp
    constexpr int NA = WN / 8;     // n-atoms per warp (even)
    extern __shared__ char dsm[];
    uint32_t dbase = (smem_u32(dsm) + 1023) & ~1023u;
    uint32_t aHi = dbase;
    uint32_t aLo = aHi + 16384;
    uint32_t wHi = aLo + 16384;
    uint32_t wLo = wHi + NT * 128;

    int t = threadIdx.x, wid = t >> 5, lane = t & 31;
    const int nperz = HD / NT;
    int z  = (mode < 0) ? (blockIdx.x / nperz) : 0;
    int n0 = (mode < 0) ? (blockIdx.x % nperz) * NT : blockIdx.x * NT;
    const float* Ap = (mode == 3) ? g_attn : A;
    const float* W  = (z == 0) ? W0 : (z == 1) ? W1 : W2;
    int storeMode   = (mode < 0) ? z : 3;

    int warp_m = wid & 1, warp_n = wid >> 1;

    float acc[4][NA][4];
#pragma unroll
    for (int i = 0; i < 4; i++)
#pragma unroll
        for (int j = 0; j < NA; j++)
#pragma unroll
            for (int q = 0; q < 4; q++) acc[i][j][q] = 0.f;

    int c4 = t & 15, r0 = t >> 4;
    // ldmatrix lane roles
    int a_rowin = lane & 15, a_kb = lane >> 4;
    int b_sub = lane >> 3, b_rowin = lane & 7;
    int b_kb = b_sub & 1, b_half = (b_sub >> 1) & 1;

    for (int ch = 0; ch < NCH; ch++) {
        int k0 = ch * KCHUNK;
        // ---- load + convert chunk ----
#pragma unroll
        for (int j = 0; j < 8; j++) {
            int r = r0 + 16 * j;
            float4 v = *(const float4*)(Ap + (size_t)r * IND + k0 + c4 * 4);
            cvt_store(aHi, aLo, r, c4, v);
        }
#pragma unroll
        for (int j = 0; j < NT / 16; j++) {
            int r = r0 + 16 * j;
            float4 v = *(const float4*)(W + (size_t)(n0 + r) * IND + k0 + c4 * 4);
            cvt_store(wHi, wLo, r, c4, v);
        }
        __syncthreads();

        // ---- 4 k-steps of 16 ----
#pragma unroll
        for (int ks = 0; ks < 4; ks++) {
            uint32_t ah[4][4], al[4][4];
#pragma unroll
            for (int i = 0; i < 4; i++) {
                int row = warp_m * 64 + i * 16 + a_rowin;
                uint32_t o = (uint32_t)(row * 128)
                           + (((uint32_t)(ks * 32 + a_kb * 16)) ^ ((uint32_t)(row & 7) << 4));
                ldsm4(ah[i], aHi + o);
                ldsm4(al[i], aLo + o);
            }
            uint32_t bh[NA][2], bl[NA][2];
#pragma unroll
            for (int p = 0; p < NA / 2; p++) {
                int row = warp_n * WN + p * 16 + b_half * 8 + b_rowin;
                uint32_t o = (uint32_t)(row * 128)
                           + (((uint32_t)(ks * 32 + b_kb * 16)) ^ ((uint32_t)(row & 7) << 4));
                uint32_t r4[4];
                ldsm4(r4, wHi + o);
                bh[2 * p][0] = r4[0]; bh[2 * p][1] = r4[1];
                bh[2 * p + 1][0] = r4[2]; bh[2 * p + 1][1] = r4[3];
                ldsm4(r4, wLo + o);
                bl[2 * p][0] = r4[0]; bl[2 * p][1] = r4[1];
                bl[2 * p + 1][0] = r4[2]; bl[2 * p + 1][1] = r4[3];
            }
#pragma unroll
            for (int i = 0; i < 4; i++)
#pragma unroll
                for (int j = 0; j < NA; j++) {
                    mma_bf16(acc[i][j], ah[i], bh[j]);
                    mma_bf16(acc[i][j], ah[i], bl[j]);
                    mma_bf16(acc[i][j], al[i], bh[j]);
                }
        }
        __syncthreads();
    }

    // ---- epilogue: fragment -> global, routed ----
    int g = lane >> 2, tq = lane & 3;
#pragma unroll
    for (int i = 0; i < 4; i++) {
#pragma unroll
        for (int j = 0; j < NA; j++) {
            int n = n0 + warp_n * WN + j * 8 + tq * 2;
#pragma unroll
            for (int half = 0; half < 2; half++) {
                int m = warp_m * 64 + i * 16 + g + half * 8;
                float2 val = make_float2(acc[i][j][2 * half], acc[i][j][2 * half + 1]);
                float* p;
                if (storeMode == 3) {
                    p = dout + (size_t)m * HD + n;
                } else {
                    int b = m >> 4, s = m & 15;
                    int h = n >> 7, dd = n & 127;
                    if (storeMode == 0) {
                        p = g_q + ((size_t)(b * HH + h) * SS + s) * DD + dd;
                    } else {
                        size_t off = (storeMode == 1) ? K_OFF : V_OFF;
                        p = dout + off + ((size_t)(b * HH + h) * KVL + PASTL + s) * DD + dd;
                    }
                }
                *(float2*)p = val;
            }
        }
    }
}

// ---------------------------------------------------------------------------
// Split-KV flash attention + fused K/V cache copy (f32x2 inner GEMMs).
// Grid (NSPLIT, 256 bh), 128 threads, ~80.4KB dyn smem, 2 blocks/SM.
// ---------------------------------------------------------------------------
__global__ __launch_bounds__(128) void flash_k(
    const float* __restrict__ kcache, const float* __restrict__ vcache,
    const int* __restrict__ mask, float* __restrict__ dout)
{
    extern __shared__ float sm[];
    float4* kvs4 = (float4*)sm;            // 4096 f4
    float4* qs4  = (float4*)(sm + 16384);  // 512 f4
    float*  ps   = sm + 18432;             // [16][132]
    float*  m_s  = sm + 20544;
    float*  l_s  = sm + 20560;
    const ulonglong2* kvsu = (const ulonglong2*)kvs4;
    const ulonglong2* qsu  = (const ulonglong2*)qs4;

    int split = blockIdx.x;
    int bh    = blockIdx.y;
    int b     = bh >> 5;
    int kv0   = split * CHUNK;
    int rows  = min(CHUNK, KVL - kv0);
    int t     = threadIdx.x;
    int lane  = t & 31;

    const float4* qsrc = (const float4*)(g_q + (size_t)bh * SS * DD);
#pragma unroll
    for (int i = t; i < 512; i += 128) qs4[i] = qsrc[i];

    float* kout = dout + K_OFF + (size_t)bh * KVL * DD;
    for (int i = t; i < rows * 32; i += 128) {
        int r = i >> 5, c = i & 31;
        int kv = kv0 + r;
        const float4* src = (kv < PASTL)
            ? (const float4*)(kcache + ((size_t)bh * PASTL + kv) * DD)
            : (const float4*)(kout + (size_t)kv * DD);
        float4 v = src[c];
        kvs4[r * 32 + (c ^ (r & 7))] = v;
        if (kv < PASTL) ((float4*)(kout + (size_t)kv * DD))[c] = v;
    }
    for (int i = rows * 32 + t; i < 128 * 32; i += 128) {
        int r = i >> 5, c = i & 31;
        kvs4[r * 32 + (c ^ (r & 7))] = make_float4(0.f, 0.f, 0.f, 0.f);
    }
    __syncthreads();

    int sgrp = t >> 5;
    int kvc  = lane;
    int s0   = sgrp * 4;
    {
        unsigned long long acc2[4][4];
#pragma unroll
        for (int i = 0; i < 4; i++)
#pragma unroll
            for (int j = 0; j < 4; j++) acc2[i][j] = 0ULL;

#pragma unroll 4
        for (int k4 = 0; k4 < 32; k4++) {
            ulonglong2 kf[4];
#pragma unroll
            for (int j = 0; j < 4; j++) {
                int kv = kvc + 32 * j;
                kf[j] = kvsu[kv * 32 + (k4 ^ (kv & 7))];
            }
#pragma unroll
            for (int i = 0; i < 4; i++) {
                ulonglong2 q = qsu[(s0 + i) * 32 + k4];
#pragma unroll
                for (int j = 0; j < 4; j++) {
                    fma2(acc2[i][j], q.x, kf[j].x);
                    fma2(acc2[i][j], q.y, kf[j].y);
                }
            }
        }

        const float scale = 0.08838834764831845f;  // 1/sqrt(128)
#pragma unroll
        for (int i = 0; i < 4; i++) {
            int s = s0 + i;
#pragma unroll
            for (int j = 0; j < 4; j++) {
                int kv  = kvc + 32 * j;
                int kvg = kv0 + kv;
                float lg;
                if (kvg >= KVL) lg = -1e30f;
                else {
                    float2 f = unpk(acc2[i][j]);
                    lg = (f.x + f.y) * scale;
                    if (mask[(size_t)(b * SS + s) * KVL + kvg] == 0) lg = -1e30f;
                }
                ps[s * 132 + kv] = lg;
            }
        }
    }
    __syncthreads();

#pragma unroll
    for (int rr = 0; rr < 4; rr++) {
        int row = sgrp * 4 + rr;
        float v = fmaxf(fmaxf(ps[row * 132 + lane], ps[row * 132 + lane + 32]),
                        fmaxf(ps[row * 132 + lane + 64], ps[row * 132 + lane + 96]));
#pragma unroll
        for (int o = 16; o > 0; o >>= 1) v = fmaxf(v, __shfl_xor_sync(0xffffffffu, v, o));
        if (lane == 0) m_s[row] = v;
    }
    __syncthreads();

#pragma unroll
    for (int i = 0; i < 4; i++) {
        float m = m_s[s0 + i];
#pragma unroll
        for (int j = 0; j < 4; j++) {
            float* p = &ps[(s0 + i) * 132 + kvc + 32 * j];
            *p = __expf(*p - m);
        }
    }
    float* vout = dout + V_OFF + (size_t)bh * KVL * DD;
    for (int i = t; i < rows * 32; i += 128) {
        int r = i >> 5, c = i & 31;
        int kv = kv0 + r;
        const float4* src = (kv < PASTL)
            ? (const float4*)(vcache + ((size_t)bh * PASTL + kv) * DD)
            : (const float4*)(vout + (size_t)kv * DD);
        float4 v = src[c];
        kvs4[r * 32 + (c ^ (r & 7))] = v;
        if (kv < PASTL) ((float4*)(vout + (size_t)kv * DD))[c] = v;
    }
    for (int i = rows * 32 + t; i < 128 * 32; i += 128) {
        int r = i >> 5, c = i & 31;
        kvs4[r * 32 + (c ^ (r & 7))] = make_float4(0.f, 0.f, 0.f, 0.f);
    }
    __syncthreads();

#pragma unroll
    for (int rr = 0; rr < 4; rr++) {
        int row = sgrp * 4 + rr;
        float v = ps[row * 132 + lane] + ps[row * 132 + lane + 32]
                + ps[row * 132 + lane + 64] + ps[row * 132 + lane + 96];
#pragma unroll
        for (int o = 16; o > 0; o >>= 1) v += __shfl_xor_sync(0xffffffffu, v, o);
        if (lane == 0) l_s[row] = v;
    }
    __syncthreads();

    {
        int dg  = lane;
        int sga = sgrp;
        unsigned long long o2[4][2];
#pragma unroll
        for (int i = 0; i < 4; i++) { o2[i][0] = 0ULL; o2[i][1] = 0ULL; }

        const float4* ps4 = (const float4*)ps;  // row stride 33 f4
#pragma unroll 4
        for (int kv4 = 0; kv4 < 32; kv4++) {
            ulonglong2 vv[4];
#pragma unroll
            for (int j = 0; j < 4; j++) {
                int kv = kv4 * 4 + j;
                vv[j] = kvsu[kv * 32 + (dg ^ (kv & 7))];
            }
#pragma unroll
            for (int i = 0; i < 4; i++) {
                float4 p4 = ps4[(sga * 4 + i) * 33 + kv4];
                unsigned long long pd;
                pd = dup2(p4.x); fma2(o2[i][0], pd, vv[0].x); fma2(o2[i][1], pd, vv[0].y);
                pd = dup2(p4.y); fma2(o2[i][0], pd, vv[1].x); fma2(o2[i][1], pd, vv[1].y);
                pd = dup2(p4.z); fma2(o2[i][0], pd, vv[2].x); fma2(o2[i][1], pd, vv[2].y);
                pd = dup2(p4.w); fma2(o2[i][0], pd, vv[3].x); fma2(o2[i][1], pd, vv[3].y);
            }
        }

        size_t base = ((size_t)split * 256 + bh) * (SS * DD);
#pragma unroll
        for (int i = 0; i < 4; i++) {
            int s = sga * 4 + i;
            float2 l0 = unpk(o2[i][0]);
            float2 l1 = unpk(o2[i][1]);
            ((float4*)(g_pacc + base + (size_t)s * DD))[dg] =
                make_float4(l0.x, l0.y, l1.x, l1.y);
        }
    }
    if (t < 16) {
        size_t idx = ((size_t)split * 256 + bh) * SS + t;
        g_pm[idx] = m_s[t];
        g_pl[idx] = l_s[t];
    }
}

// ---------------------------------------------------------------------------
// Combine split partials -> g_attn. Grid 256 (bh), 512 threads (s, dg).
// ---------------------------------------------------------------------------
__global__ __launch_bounds__(512) void combine_k()
{
    int bh = blockIdx.x;
    int t  = threadIdx.x;
    int dg = t & 31, s = t >> 5;
    int b = bh >> 5, h = bh & 31;

    float M = -3.4e38f;
#pragma unroll 11
    for (int sp = 0; sp < NSPLIT; sp++)
        M = fmaxf(M, g_pm[((size_t)sp * 256 + bh) * SS + s]);
    float lsum = 0.f;
    float4 o = make_float4(0.f, 0.f, 0.f, 0.f);
#pragma unroll 11
    for (int sp = 0; sp < NSPLIT; sp++) {
        size_t idx = (size_t)sp * 256 + bh;
        float f = __expf(g_pm[idx * SS + s] - M);
        lsum += f * g_pl[idx * SS + s];
        float4 a = ((const float4*)(g_pacc + idx * (SS * DD) + (size_t)s * DD))[dg];
        o.x += f * a.x; o.y += f * a.y; o.z += f * a.z; o.w += f * a.w;
    }
    float inv = 1.0f / lsum;
    o.x *= inv; o.y *= inv; o.z *= inv; o.w *= inv;
    ((float4*)(g_attn + ((size_t)(b * SS + s)) * HD + h * DD))[dg] = o;
}

// ---------------------------------------------------------------------------
extern "C" void kernel_launch(void* const* d_in, const int* in_sizes, int n_in,
                              void* d_out, int out_size)
{
    const float* hidden = (const float*)d_in[0];
    const int*   mask   = (const int*)d_in[1];
    const float* kcache = (const float*)d_in[2];
    const float* vcache = (const float*)d_in[3];
    const float* Wq     = (const float*)d_in[4];
    const float* Wk     = (const float*)d_in[5];
    const float* Wv     = (const float*)d_in[6];
    const float* Wo     = (const float*)d_in[7];
    float* out = (float*)d_out;

    const int FLASH_SMEM = (16384 + 2048 + 2112 + 32) * 4;   // 82304 B
    const int SM128 = 1024 + 32768 + 2 * 128 * 128;          // 66560 B
    const int SM64  = 1024 + 32768 + 2 * 64 * 128;           // 50176 B
    cudaFuncSetAttribute(flash_k, cudaFuncAttributeMaxDynamicSharedMemorySize,
                         FLASH_SMEM);
    cudaFuncSetAttribute(gemm_mma<128>, cudaFuncAttributeMaxDynamicSharedMemorySize,
                         SM128);
    cudaFuncSetAttribute(gemm_mma<64>, cudaFuncAttributeMaxDynamicSharedMemorySize,
                         SM64);

    // 1. QKV projections on tensor cores (q -> scratch, k_new/v_new -> out)
    gemm_mma<128><<<96, 256, SM128>>>(hidden, Wq, Wk, Wv, out, -1);
    // 2. Split-KV flash attention + fused K/V cache copies
    flash_k<<<dim3(NSPLIT, 256), 128, FLASH_SMEM>>>(kcache, vcache, mask, out);
    // 3. Combine flash partials
    combine_k<<<256, 512>>>();
    // 4. Output projection on tensor cores
    gemm_mma<64><<<64, 256, SM64>>>(nullptr, Wo, Wo, Wo, out, 3);
}